// round 9
// baseline (speedup 1.0000x reference)
#include <cuda_runtime.h>
#include <cuda_fp16.h>
#include <cstdint>

// ---------------- problem constants ----------------
#define DIMV   96
#define PVOX   (96*96*96)            // 884736 positions
#define CCH    32
#define NB     2
#define NPERB  30000
#define NVTOT  60000
#define VPB    16                    // vertices per group (= warps per block)
#define NGROUPS (NVTOT/VPB)          // 3750
#define NSM    152
#define ITOT   864                   // C*27 reduction length (k' = tap*32 + c)

// smem layout (bytes). Row strides 2064 == 16 mod 128 -> conflict-free LDSM.
#define WSTRB  2064
#define FSTRB  2064
#define WH_BYTES  (32*WSTRB)         // 66048
#define STG_ROW   256                // staging row: 4 positions x 64B
#define STG_V     (16*STG_ROW)       // 4096 per vertex
#define STG_BYTES (VPB*STG_V)        // 65536
#define FS_BYTES  (VPB*FSTRB)        // 33024
#define OSTR   36                    // part row stride (floats)
#define PARTW  (16*OSTR)
#define PART_BYTES (16*PARTW*4)      // 36864
#define OFF_W    0
#define OFF_STG  (OFF_W + WH_BYTES)
#define OFF_FS   (OFF_STG + STG_BYTES)
#define OFF_PART (OFF_FS + FS_BYTES)
#define SMEM_BYTES (OFF_PART + PART_BYTES)   // 201472

// Scratch: transposed voxel features (B,H,W,D,C) fp16 (113 MB)
__device__ __half g_vt[(size_t)NB * PVOX * CCH];

static __device__ __forceinline__ uint32_t smem_u32(const void* p) {
    uint32_t a;
    asm("{ .reg .u64 t; cvta.to.shared.u64 t, %1; cvt.u32.u64 %0, t; }" : "=r"(a) : "l"(p));
    return a;
}
static __device__ __forceinline__ void cp_async16(uint32_t dst, const void* src) {
    asm volatile("cp.async.cg.shared.global [%0], [%1], 16;" :: "r"(dst), "l"(src));
}
static __device__ __forceinline__ void cp_commit() {
    asm volatile("cp.async.commit_group;");
}
static __device__ __forceinline__ void cp_wait0() {
    asm volatile("cp.async.wait_group 0;");
}
static __device__ __forceinline__ void ldsm_x4(
    uint32_t& r0, uint32_t& r1, uint32_t& r2, uint32_t& r3, uint32_t addr) {
    asm volatile("ldmatrix.sync.aligned.m8n8.x4.shared.b16 {%0,%1,%2,%3}, [%4];"
                 : "=r"(r0), "=r"(r1), "=r"(r2), "=r"(r3) : "r"(addr));
}
static __device__ __forceinline__ void mma16816(
    float& c0, float& c1, float& c2, float& c3,
    uint32_t a0, uint32_t a1, uint32_t a2, uint32_t a3,
    uint32_t b0, uint32_t b1) {
    asm volatile(
        "mma.sync.aligned.m16n8k16.row.col.f32.f16.f16.f32 "
        "{%0,%1,%2,%3}, {%4,%5,%6,%7}, {%8,%9}, {%0,%1,%2,%3};"
        : "+f"(c0), "+f"(c1), "+f"(c2), "+f"(c3)
        : "r"(a0), "r"(a1), "r"(a2), "r"(a3), "r"(b0), "r"(b1));
}

// ---------------------------------------------------------------------------
// Kernel 1: transpose (B,C,P) fp32 -> (B,P,C) fp16, register transpose.
// ---------------------------------------------------------------------------
__global__ void __launch_bounds__(256) transpose_kernel(
    const float* __restrict__ in, __half* __restrict__ vt) {
    const int b    = blockIdx.y;
    const int warp = threadIdx.x >> 5;
    const int lane = threadIdx.x & 31;
    const int p0   = (blockIdx.x * 8 + warp) * 32;

    const float* ib = in + (size_t)b * CCH * PVOX + p0 + lane;
    __half2 h[16];
#pragma unroll
    for (int c = 0; c < 32; c += 2) {
        float v0 = __ldg(ib + (size_t)c * PVOX);
        float v1 = __ldg(ib + (size_t)(c + 1) * PVOX);
        h[c >> 1] = __floats2half2_rn(v0, v1);
    }
    uint4* ob = reinterpret_cast<uint4*>(vt + ((size_t)b * PVOX + p0 + lane) * CCH);
    const uint4* hs = reinterpret_cast<const uint4*>(h);
#pragma unroll
    for (int k = 0; k < 4; k++) ob[k] = hs[k];
}

// ---------------------------------------------------------------------------
// Kernel 2: persistent fused sample + conv; cp.async pipelined gather,
// LDSM-fed HMMA, tap-major k ordering (k' = tap*32 + c), 2 barriers/group.
// ---------------------------------------------------------------------------
__global__ void __launch_bounds__(512, 1) fused_kernel(
    const __half* __restrict__ vt,
    const float* __restrict__ verts,
    const float* __restrict__ Wg,      // (32,32,1,27): o*864 + c*27 + tap
    const float* __restrict__ bias,
    float* __restrict__ out) {
    extern __shared__ char smc[];
    char*  smw  = smc + OFF_W;           // W fp16 [32 o][k' halves]
    char*  smf  = smc + OFF_FS;          // feats fp16 [16 v][k' halves]
    float* part = (float*)(smc + OFF_PART);

    const int tid  = threadIdx.x;
    const int warp = tid >> 5;
    const int lane = tid & 31;
    const uint32_t stgW = smem_u32(smc + OFF_STG) + warp * STG_V;

    // ---- one-time: stage W permuted to k' = tap*32 + c, zero K-pad --------
    for (int g = tid; g < 32 * (WSTRB / 4); g += 512) {
        int o = g / (WSTRB / 4);
        int w = g - o * (WSTRB / 4);
        float w0 = 0.f, w1 = 0.f;
        int k0 = w * 2;
        if (k0 < ITOT) {
            int c = k0 & 31, tap = k0 >> 5;
            w0 = Wg[(size_t)o * ITOT + c * 27 + tap];
        }
        if (k0 + 1 < ITOT) {
            int c = (k0 + 1) & 31, tap = (k0 + 1) >> 5;
            w1 = Wg[(size_t)o * ITOT + c * 27 + tap];
        }
        __half2 hv = __floats2half2_rn(w0, w1);
        *reinterpret_cast<uint32_t*>(smw + (size_t)o * WSTRB + w * 4) =
            *reinterpret_cast<uint32_t*>(&hv);
    }
    // feats: zero pad words [ITOT/2, FSTRB/4) of every vertex row
    for (int g = tid; g < VPB * (FSTRB / 4 - ITOT / 2); g += 512) {
        int v = g / (FSTRB / 4 - ITOT / 2);
        int j = g - v * (FSTRB / 4 - ITOT / 2) + ITOT / 2;
        *reinterpret_cast<uint32_t*>(smf + (size_t)v * FSTRB + j * 4) = 0u;
    }
    __syncthreads();

    // LDSM address bases (lane-dependent, loop-invariant)
    const int lt = lane >> 3, lr = lane & 7;
    const uint32_t smf_b = smem_u32(smf);
    const uint32_t smw_b = smem_u32(smw);
    const uint32_t aoff  = smf_b + (uint32_t)(lr + ((lt & 1) << 3)) * FSTRB + ((lt >> 1) << 4);
    const uint32_t boff0 = smw_b + (uint32_t)((lt >> 1) * 8 + lr) * WSTRB + ((lt & 1) << 4);
    const uint32_t boff1 = boff0 + 16 * WSTRB;

    const int gq = lane >> 2;   // output frag row
    const int qq = lane & 3;
    const int rsel = lane >> 4; // staging copy helpers
    const int ln16 = lane & 15;
    const float bias_r = __ldg(bias + lane);

    // staged-group coords (per warp's vertex)
    float sfx = 0.f, sfy = 0.f, sfz = 0.f;
    int ssx0 = 0, ssx1 = 0, ssx2 = 0, ssx3 = 0;

    auto stage = [&](int grp) {
        const int vglob = grp * VPB + warp;
        const int b = vglob / NPERB;
        const float vx = verts[(size_t)vglob * 3 + 0];
        const float vy = verts[(size_t)vglob * 3 + 1];
        const float vz = verts[(size_t)vglob * 3 + 2];

        int xlo, cnt16;
        {
            float f = fminf(fmaxf((vx + 1.f) * 47.5f, 0.f), 95.f);
            int i0 = (int)f; sfx = f - (float)i0;
            xlo = max(i0 - 1, 0);
            int xhi = min(i0 + 2, 95);
            cnt16 = (xhi - xlo + 1) * 4;
            ssx0 = max(i0 - 1, 0) - xlo;
            ssx1 = i0 - xlo;
            ssx2 = min(i0 + 1, 95) - xlo;
            ssx3 = min(i0 + 2, 95) - xlo;
        }
        int yp[4], zp[4];
        {
            float f = fminf(fmaxf((vy + 1.f) * 47.5f, 0.f), 95.f);
            int i0 = (int)f; sfy = f - (float)i0;
#pragma unroll
            for (int j = 0; j < 4; j++) yp[j] = min(max(i0 - 1 + j, 0), 95);
        }
        {
            float f = fminf(fmaxf((vz + 1.f) * 47.5f, 0.f), 95.f);
            int i0 = (int)f; sfz = f - (float)i0;
#pragma unroll
            for (int j = 0; j < 4; j++) zp[j] = min(max(i0 - 1 + j, 0), 95);
        }
        const char* vb = (const char*)(vt + ((size_t)b * PVOX) * CCH);
        const bool on = (ln16 < cnt16);
#pragma unroll
        for (int step = 0; step < 8; step++) {
            int row = step * 2 + rsel;
            int jz = row >> 2, jy = row & 3;
            size_t pos = ((size_t)zp[jz] * (DIMV * DIMV) + (size_t)yp[jy] * DIMV + xlo);
            const char* src = vb + pos * (CCH * 2) + ln16 * 16;
            uint32_t dst = stgW + row * STG_ROW + ln16 * 16;
            if (on) cp_async16(dst, src);
        }
        cp_commit();
    };

    stage(blockIdx.x);

    for (int grp = blockIdx.x; grp < NGROUPS; grp += NSM) {
        const float fx = sfx, fy = sfy, fz = sfz;
        const int sx[4] = {ssx0, ssx1, ssx2, ssx3};
        const int vglob = grp * VPB + warp;
        const int b = vglob / NPERB;
        const int n = vglob - b * NPERB;

        cp_wait0();   // own staged rows resident (warp-private)

        // ---- interp from staging -> feats fp16 (k' = tap*32 + lane) -------
        {
            const float omfz = 1.f - fz;
            float acc[27];
#pragma unroll
            for (int kk = 0; kk < 27; kk++) acc[kk] = 0.f;

            const __half* stg = reinterpret_cast<const __half*>(
                smc + OFF_STG + warp * STG_V);
#pragma unroll
            for (int jz = 0; jz < 4; jz++) {
                float t4[12];
#pragma unroll
                for (int jy = 0; jy < 4; jy++) {
                    const __half* r = stg + ((jz * 4 + jy) * STG_ROW) / 2 + lane;
                    float a0 = __half2float(r[sx[0] * 32]);
                    float a1 = __half2float(r[sx[1] * 32]);
                    float a2 = __half2float(r[sx[2] * 32]);
                    float a3 = __half2float(r[sx[3] * 32]);
                    t4[jy * 3 + 0] = a0 + fx * (a1 - a0);
                    t4[jy * 3 + 1] = a1 + fx * (a2 - a1);
                    t4[jy * 3 + 2] = a2 + fx * (a3 - a2);
                }
#pragma unroll
                for (int dy = 0; dy < 3; dy++) {
#pragma unroll
                    for (int dxx = 0; dxx < 3; dxx++) {
                        float a  = t4[dy * 3 + dxx];
                        float bq = t4[(dy + 1) * 3 + dxx];
                        float ly = a + fy * (bq - a);
                        if (jz < 3) acc[dxx * 9 + dy * 3 + jz]       += omfz * ly;
                        if (jz > 0) acc[dxx * 9 + dy * 3 + (jz - 1)] += fz   * ly;
                    }
                }
            }
            __half* fr = reinterpret_cast<__half*>(smf + (size_t)warp * FSTRB);
#pragma unroll
            for (int kk = 0; kk < 27; kk++)
                fr[kk * 32 + lane] = __float2half_rn(acc[kk]);   // clean 64B stores
        }

        // prefetch next group's gather (own slab already consumed)
        const int nxt = grp + NSM;
        if (nxt < NGROUPS) stage(nxt);

        __syncthreads();   // sync1: all feats visible

        // ---- HMMA conv via ldmatrix.x4 ------------------------------------
        {
            float c[4][4];
#pragma unroll
            for (int nt = 0; nt < 4; nt++)
#pragma unroll
                for (int r = 0; r < 4; r++) c[nt][r] = 0.f;

#pragma unroll
            for (int t = 0; t < 4; t++) {
                const uint32_t kb = (warp * 4 + t) * 32;
                uint32_t a0, a1, a2, a3;
                ldsm_x4(a0, a1, a2, a3, aoff + kb);
                uint32_t b00, b01, b10, b11, b20, b21, b30, b31;
                ldsm_x4(b00, b01, b10, b11, boff0 + kb);
                ldsm_x4(b20, b21, b30, b31, boff1 + kb);
                mma16816(c[0][0], c[0][1], c[0][2], c[0][3], a0, a1, a2, a3, b00, b01);
                mma16816(c[1][0], c[1][1], c[1][2], c[1][3], a0, a1, a2, a3, b10, b11);
                mma16816(c[2][0], c[2][1], c[2][2], c[2][3], a0, a1, a2, a3, b20, b21);
                mma16816(c[3][0], c[3][1], c[3][2], c[3][3], a0, a1, a2, a3, b30, b31);
            }
            float* pw = part + (size_t)warp * PARTW;
#pragma unroll
            for (int nt = 0; nt < 4; nt++) {
                *reinterpret_cast<float2*>(pw + gq * OSTR + nt * 8 + qq * 2) =
                    make_float2(c[nt][0], c[nt][1]);
                *reinterpret_cast<float2*>(pw + (gq + 8) * OSTR + nt * 8 + qq * 2) =
                    make_float2(c[nt][2], c[nt][3]);
            }
        }
        __syncthreads();   // sync2: all partials visible

        // ---- reduce + bias, store (no trailing barrier needed) ------------
        {
            float s = bias_r;
#pragma unroll
            for (int w2 = 0; w2 < 16; w2++)
                s += part[(size_t)w2 * PARTW + warp * OSTR + lane];
            out[((size_t)b * NPERB + n) * 32 + lane] = s;
        }
        // NOTE: no sync3. feats rewrites are fenced by sync2 of this group
        // (HMMA reads completed) and part rewrites by sync1 of next group
        // (reached only after every warp's reduce).
    }
}

// ---------------------------------------------------------------------------
extern "C" void kernel_launch(void* const* d_in, const int* in_sizes, int n_in,
                              void* d_out, int out_size) {
    const float* vox   = (const float*)d_in[0];   // (2,32,96,96,96)
    const float* verts = (const float*)d_in[1];   // (2,30000,3)
    const float* Wg    = (const float*)d_in[2];   // (32,32,1,27)
    const float* bias  = (const float*)d_in[3];   // (32,)
    float* out = (float*)d_out;

    __half* vt = nullptr;
    cudaGetSymbolAddress((void**)&vt, g_vt);

    cudaFuncSetAttribute(fused_kernel,
                         cudaFuncAttributeMaxDynamicSharedMemorySize, SMEM_BYTES);

    transpose_kernel<<<dim3(PVOX / 256, NB), 256>>>(vox, vt);
    fused_kernel<<<NSM, 512, SMEM_BYTES>>>(vt, verts, Wg, bias, out);
}

// round 11
// speedup vs baseline: 1.0204x; 1.0204x over previous
#include <cuda_runtime.h>
#include <cuda_fp16.h>
#include <cstdint>

// ---------------- problem constants ----------------
#define DIMV   96
#define PVOX   (96*96*96)            // 884736 positions
#define CCH    32
#define NB     2
#define NPERB  30000
#define NVTOT  60000
#define OCT    8                     // vertices per octet (= warps per domain)
#define NOCT   (NVTOT/OCT)           // 7500
#define NSM    152
#define NSTREAMS (2*NSM)             // 304 independent octet streams
#define ITOT   864                   // reduction length (k' = tap*32 + c)
#define KH     896                   // padded K halves (56 k16-steps, 7/warp)

// smem layout (bytes)
#define WSTRB  2064                  // W row stride (==16 mod 128)
#define FSTRB2 1808                  // feats row stride (==16 mod 128), 904 halves
#define WH_BYTES  (32*WSTRB)         // 66048
#define STG_ROW   256
#define STG_V     (16*STG_ROW)       // 4096 per warp
#define STG_BYTES (16*STG_V)         // 65536
#define FS_DOM    (OCT*FSTRB2)       // 14464 per domain
#define FS_BYTES  (2*FS_DOM)         // 28928
#define OSTR   36                    // part row stride (floats)
#define PART_DOM  (OCT*OCT*OSTR*4)   // 9216 B per domain [8 warps][8 v][36]
#define PART_BYTES (2*PART_DOM)      // 18432
#define OFF_W    0
#define OFF_STG  (OFF_W + WH_BYTES)
#define OFF_FS   (OFF_STG + STG_BYTES)
#define OFF_PART (OFF_FS + FS_BYTES)
#define SMEM_BYTES (OFF_PART + PART_BYTES)   // 178944

// Scratch: transposed voxel features (B,H,W,D,C) fp16 (113 MB)
__device__ __half g_vt[(size_t)NB * PVOX * CCH];

static __device__ __forceinline__ uint32_t smem_u32(const void* p) {
    uint32_t a;
    asm("{ .reg .u64 t; cvta.to.shared.u64 t, %1; cvt.u32.u64 %0, t; }" : "=r"(a) : "l"(p));
    return a;
}
static __device__ __forceinline__ void cp_async16(uint32_t dst, const void* src) {
    asm volatile("cp.async.cg.shared.global [%0], [%1], 16;" :: "r"(dst), "l"(src));
}
static __device__ __forceinline__ void cp_commit() {
    asm volatile("cp.async.commit_group;");
}
static __device__ __forceinline__ void cp_wait0() {
    asm volatile("cp.async.wait_group 0;");
}
static __device__ __forceinline__ void bar_dom(int id) {
    asm volatile("bar.sync %0, 256;" :: "r"(id) : "memory");
}
static __device__ __forceinline__ void ldsm_x4(
    uint32_t& r0, uint32_t& r1, uint32_t& r2, uint32_t& r3, uint32_t addr) {
    asm volatile("ldmatrix.sync.aligned.m8n8.x4.shared.b16 {%0,%1,%2,%3}, [%4];"
                 : "=r"(r0), "=r"(r1), "=r"(r2), "=r"(r3) : "r"(addr));
}
static __device__ __forceinline__ void mma16816(
    float& c0, float& c1, float& c2, float& c3,
    uint32_t a0, uint32_t a1, uint32_t a2, uint32_t a3,
    uint32_t b0, uint32_t b1) {
    asm volatile(
        "mma.sync.aligned.m16n8k16.row.col.f32.f16.f16.f32 "
        "{%0,%1,%2,%3}, {%4,%5,%6,%7}, {%8,%9}, {%0,%1,%2,%3};"
        : "+f"(c0), "+f"(c1), "+f"(c2), "+f"(c3)
        : "r"(a0), "r"(a1), "r"(a2), "r"(a3), "r"(b0), "r"(b1));
}

// ---------------------------------------------------------------------------
// Kernel 1: transpose (B,C,P) fp32 -> (B,P,C) fp16, register transpose.
// ---------------------------------------------------------------------------
__global__ void __launch_bounds__(256) transpose_kernel(
    const float* __restrict__ in, __half* __restrict__ vt) {
    const int b    = blockIdx.y;
    const int warp = threadIdx.x >> 5;
    const int lane = threadIdx.x & 31;
    const int p0   = (blockIdx.x * 8 + warp) * 32;

    const float* ib = in + (size_t)b * CCH * PVOX + p0 + lane;
    __half2 h[16];
#pragma unroll
    for (int c = 0; c < 32; c += 2) {
        float v0 = __ldg(ib + (size_t)c * PVOX);
        float v1 = __ldg(ib + (size_t)(c + 1) * PVOX);
        h[c >> 1] = __floats2half2_rn(v0, v1);
    }
    uint4* ob = reinterpret_cast<uint4*>(vt + ((size_t)b * PVOX + p0 + lane) * CCH);
    const uint4* hs = reinterpret_cast<const uint4*>(h);
#pragma unroll
    for (int k = 0; k < 4; k++) ob[k] = hs[k];
}

// ---------------------------------------------------------------------------
// Kernel 2: persistent fused sample + conv. 16 warps = 2 independent 8-warp
// domains (named barriers), each streaming 8-vertex octets. cp.async
// pipelined gather, LDSM-fed HMMA (M=16 frag, 8 valid rows), tap-major k.
// ---------------------------------------------------------------------------
__global__ void __launch_bounds__(512, 1) fused_kernel(
    const __half* __restrict__ vt,
    const float* __restrict__ verts,
    const float* __restrict__ Wg,      // (32,32,1,27): o*864 + c*27 + tap
    const float* __restrict__ bias,
    float* __restrict__ out) {
    extern __shared__ char smc[];
    char* smw = smc + OFF_W;

    const int tid  = threadIdx.x;
    const int warp = tid >> 5;
    const int lane = tid & 31;
    const int dom  = warp >> 3;         // 0 / 1
    const int wd   = warp & 7;          // warp within domain = vertex slot
    const int barid = 1 + dom;

    char*  smf  = smc + OFF_FS + dom * FS_DOM;            // feats [8][FSTRB2]
    float* part = (float*)(smc + OFF_PART + dom * PART_DOM); // [8][8][OSTR]
    const uint32_t stgW = smem_u32(smc + OFF_STG) + warp * STG_V;

    // ---- one-time: stage W permuted to k' = tap*32 + c, zero K-pad --------
    for (int g = tid; g < 32 * (WSTRB / 4); g += 512) {
        int o = g / (WSTRB / 4);
        int w = g - o * (WSTRB / 4);
        float w0 = 0.f, w1 = 0.f;
        int k0 = w * 2;
        if (k0 < ITOT) {
            int c = k0 & 31, tap = k0 >> 5;
            w0 = Wg[(size_t)o * ITOT + c * 27 + tap];
        }
        if (k0 + 1 < ITOT) {
            int c = (k0 + 1) & 31, tap = (k0 + 1) >> 5;
            w1 = Wg[(size_t)o * ITOT + c * 27 + tap];
        }
        __half2 hv = __floats2half2_rn(w0, w1);
        *reinterpret_cast<uint32_t*>(smw + (size_t)o * WSTRB + w * 4) =
            *reinterpret_cast<uint32_t*>(&hv);
    }
    // feats: zero pad halves [ITOT, 2*(FSTRB2/4)*2) of every row, both domains
    for (int g = tid; g < 2 * OCT * (FSTRB2 / 4 - ITOT / 2); g += 512) {
        const int wpr = FSTRB2 / 4 - ITOT / 2;    // pad words per row (20)
        int row = g / wpr;
        int j   = g - row * wpr + ITOT / 2;
        *reinterpret_cast<uint32_t*>(smc + OFF_FS + (size_t)row * FSTRB2 + j * 4) = 0u;
    }
    __syncthreads();

    // LDSM bases (loop-invariant). A: tiles 0/1 both -> rows 0-7 (dup).
    const int lt = lane >> 3, lr = lane & 7;
    const uint32_t smf_b = smem_u32(smf);
    const uint32_t smw_b = smem_u32(smw);
    const uint32_t aoff  = smf_b + (uint32_t)lr * FSTRB2 + ((lt >> 1) << 4);
    const uint32_t boff0 = smw_b + (uint32_t)((lt >> 1) * 8 + lr) * WSTRB + ((lt & 1) << 4);
    const uint32_t boff1 = boff0 + 16 * WSTRB;

    const int gq = lane >> 2;     // output frag row (vertex) 0..7
    const int qq = lane & 3;
    const int rsel = lane >> 4;   // staging helpers
    const int ln16 = lane & 15;
    const float bias_r = __ldg(bias + lane);

    // staged coords for this warp's vertex
    float sfx = 0.f, sfy = 0.f, sfz = 0.f;
    int ssx0 = 0, ssx1 = 0, ssx2 = 0, ssx3 = 0;

    auto stage = [&](int oct) {
        const int vglob = oct * OCT + wd;
        const int b = vglob / NPERB;
        const float vx = verts[(size_t)vglob * 3 + 0];
        const float vy = verts[(size_t)vglob * 3 + 1];
        const float vz = verts[(size_t)vglob * 3 + 2];

        int xlo, cnt16;
        {
            float f = fminf(fmaxf((vx + 1.f) * 47.5f, 0.f), 95.f);
            int i0 = (int)f; sfx = f - (float)i0;
            xlo = max(i0 - 1, 0);
            int xhi = min(i0 + 2, 95);
            cnt16 = (xhi - xlo + 1) * 4;
            ssx0 = max(i0 - 1, 0) - xlo;
            ssx1 = i0 - xlo;
            ssx2 = min(i0 + 1, 95) - xlo;
            ssx3 = min(i0 + 2, 95) - xlo;
        }
        int yp[4], zp[4];
        {
            float f = fminf(fmaxf((vy + 1.f) * 47.5f, 0.f), 95.f);
            int i0 = (int)f; sfy = f - (float)i0;
#pragma unroll
            for (int j = 0; j < 4; j++) yp[j] = min(max(i0 - 1 + j, 0), 95);
        }
        {
            float f = fminf(fmaxf((vz + 1.f) * 47.5f, 0.f), 95.f);
            int i0 = (int)f; sfz = f - (float)i0;
#pragma unroll
            for (int j = 0; j < 4; j++) zp[j] = min(max(i0 - 1 + j, 0), 95);
        }
        const char* vb = (const char*)(vt + ((size_t)b * PVOX) * CCH);
        const bool on = (ln16 < cnt16);
#pragma unroll
        for (int step = 0; step < 8; step++) {
            int row = step * 2 + rsel;
            int jz = row >> 2, jy = row & 3;
            size_t pos = ((size_t)zp[jz] * (DIMV * DIMV) + (size_t)yp[jy] * DIMV + xlo);
            const char* src = vb + pos * (CCH * 2) + ln16 * 16;
            uint32_t dst = stgW + row * STG_ROW + ln16 * 16;
            if (on) cp_async16(dst, src);
        }
        cp_commit();
    };

    const int oct0 = blockIdx.x * 2 + dom;   // this domain's stream
    stage(oct0);

    for (int oct = oct0; oct < NOCT; oct += NSTREAMS) {
        const float fx = sfx, fy = sfy, fz = sfz;
        const int sx[4] = {ssx0, ssx1, ssx2, ssx3};
        const int vglob = oct * OCT + wd;

        cp_wait0();   // own staged rows resident (warp-private)

        // ---- interp from staging -> feats fp16 (k' = tap*32 + lane) -------
        {
            const float omfz = 1.f - fz;
            float acc[27];
#pragma unroll
            for (int kk = 0; kk < 27; kk++) acc[kk] = 0.f;

            const __half* stg = reinterpret_cast<const __half*>(
                smc + OFF_STG + warp * STG_V);
#pragma unroll
            for (int jz = 0; jz < 4; jz++) {
                float t4[12];
#pragma unroll
                for (int jy = 0; jy < 4; jy++) {
                    const __half* r = stg + ((jz * 4 + jy) * STG_ROW) / 2 + lane;
                    float a0 = __half2float(r[sx[0] * 32]);
                    float a1 = __half2float(r[sx[1] * 32]);
                    float a2 = __half2float(r[sx[2] * 32]);
                    float a3 = __half2float(r[sx[3] * 32]);
                    t4[jy * 3 + 0] = a0 + fx * (a1 - a0);
                    t4[jy * 3 + 1] = a1 + fx * (a2 - a1);
                    t4[jy * 3 + 2] = a2 + fx * (a3 - a2);
                }
#pragma unroll
                for (int dy = 0; dy < 3; dy++) {
#pragma unroll
                    for (int dxx = 0; dxx < 3; dxx++) {
                        float a  = t4[dy * 3 + dxx];
                        float bq = t4[(dy + 1) * 3 + dxx];
                        float ly = a + fy * (bq - a);
                        if (jz < 3) acc[dxx * 9 + dy * 3 + jz]       += omfz * ly;
                        if (jz > 0) acc[dxx * 9 + dy * 3 + (jz - 1)] += fz   * ly;
                    }
                }
            }
            __half* fr = reinterpret_cast<__half*>(smf + (size_t)wd * FSTRB2);
#pragma unroll
            for (int kk = 0; kk < 27; kk++)
                fr[kk * 32 + lane] = __float2half_rn(acc[kk]);
        }

        // prefetch next octet of this stream (own slab already consumed)
        const int nxt = oct + NSTREAMS;
        if (nxt < NOCT) stage(nxt);

        bar_dom(barid);   // sync1: domain feats visible

        // ---- HMMA conv (M=16 frag, rows 0-7 valid) ------------------------
        {
            float c[4][4];
#pragma unroll
            for (int nt = 0; nt < 4; nt++)
#pragma unroll
                for (int r = 0; r < 4; r++) c[nt][r] = 0.f;

#pragma unroll
            for (int t = 0; t < 7; t++) {
                const uint32_t kb = (wd * 7 + t) * 32;
                uint32_t a0, a1, a2, a3;
                ldsm_x4(a0, a1, a2, a3, aoff + kb);
                uint32_t b00, b01, b10, b11, b20, b21, b30, b31;
                ldsm_x4(b00, b01, b10, b11, boff0 + kb);
                ldsm_x4(b20, b21, b30, b31, boff1 + kb);
                mma16816(c[0][0], c[0][1], c[0][2], c[0][3], a0, a1, a2, a3, b00, b01);
                mma16816(c[1][0], c[1][1], c[1][2], c[1][3], a0, a1, a2, a3, b10, b11);
                mma16816(c[2][0], c[2][1], c[2][2], c[2][3], a0, a1, a2, a3, b20, b21);
                mma16816(c[3][0], c[3][1], c[3][2], c[3][3], a0, a1, a2, a3, b30, b31);
            }
            float* pw = part + (size_t)wd * (OCT * OSTR);
#pragma unroll
            for (int nt = 0; nt < 4; nt++)
                *reinterpret_cast<float2*>(pw + gq * OSTR + nt * 8 + qq * 2) =
                    make_float2(c[nt][0], c[nt][1]);   // rows 0-7 only
        }
        bar_dom(barid);   // sync2: domain partials visible

        // ---- reduce + bias, store -----------------------------------------
        {
            float s = bias_r;
#pragma unroll
            for (int w2 = 0; w2 < 8; w2++)
                s += part[(size_t)w2 * (OCT * OSTR) + wd * OSTR + lane];
            out[(size_t)vglob * 32 + lane] = s;
        }
        // no trailing barrier: feats rewrite fenced by this sync2, part
        // rewrite fenced by next iteration's sync1 (all warps passed reduce).
    }
}

// ---------------------------------------------------------------------------
extern "C" void kernel_launch(void* const* d_in, const int* in_sizes, int n_in,
                              void* d_out, int out_size) {
    const float* vox   = (const float*)d_in[0];   // (2,32,96,96,96)
    const float* verts = (const float*)d_in[1];   // (2,30000,3)
    const float* Wg    = (const float*)d_in[2];   // (32,32,1,27)
    const float* bias  = (const float*)d_in[3];   // (32,)
    float* out = (float*)d_out;

    __half* vt = nullptr;
    cudaGetSymbolAddress((void**)&vt, g_vt);

    cudaFuncSetAttribute(fused_kernel,
                         cudaFuncAttributeMaxDynamicSharedMemorySize, SMEM_BYTES);

    transpose_kernel<<<dim3(PVOX / 256, NB), 256>>>(vox, vt);
    fused_kernel<<<NSM, 512, SMEM_BYTES>>>(vt, verts, Wg, bias, out);
}